// round 8
// baseline (speedup 1.0000x reference)
#include <cuda_runtime.h>
#include <cuda_bf16.h>
#include <stdint.h>
#include <math.h>

// Problem constants
#define BATCH 4
#define SEQ   2048
#define EMB   1024
#define HEAD  64
#define NROWS (BATCH * SEQ)   // 8192
#define SPLITK 4

// ---------------- scratch ----------------
__device__ float g_q[NROWS * HEAD];   // tf32-rounded
__device__ float g_k[NROWS * HEAD];   // tf32-rounded
__device__ float g_v[NROWS * HEAD];   // tf32-rounded
__device__ float g_om[SPLITK * NROWS * HEAD];
__device__ float g_m [SPLITK * NROWS];
__device__ float g_l [SPLITK * NROWS];
__device__ float g_w [192 * EMB];     // gamma-folded, tf32-rounded weights (q|k|v)
__device__ float g_wsum [192];
__device__ float g_wbeta[192];

__device__ __forceinline__ uint32_t f2tf32(float f) {
    uint32_t r;
    asm("cvt.rna.tf32.f32 %0, %1;" : "=r"(r) : "f"(f));
    return r;
}
__device__ __forceinline__ float tf32r(float f) { return __uint_as_float(f2tf32(f)); }

__device__ __forceinline__ void mma_tf32(float* d, const uint32_t* a,
                                         uint32_t b0, uint32_t b1) {
    asm volatile(
        "mma.sync.aligned.m16n8k8.row.col.f32.tf32.tf32.f32 "
        "{%0,%1,%2,%3}, {%4,%5,%6,%7}, {%8,%9}, {%0,%1,%2,%3};"
        : "+f"(d[0]), "+f"(d[1]), "+f"(d[2]), "+f"(d[3])
        : "r"(a[0]), "r"(a[1]), "r"(a[2]), "r"(a[3]), "r"(b0), "r"(b1));
}

__device__ __forceinline__ uint32_t smem_u32(const void* p) {
    return (uint32_t)__cvta_generic_to_shared(p);
}

#define CP_ASYNC16(dst_u32, src_ptr) \
    asm volatile("cp.async.cg.shared.global [%0], [%1], 16;" \
                 :: "r"(dst_u32), "l"(src_ptr))
#define CP_COMMIT() asm volatile("cp.async.commit_group;")
#define CP_WAIT(N)  asm volatile("cp.async.wait_group %0;" :: "n"(N))

// ================= Kernel 0: weight prep =================
__global__ void __launch_bounds__(256)
wprep_kernel(const float* __restrict__ gamma,
             const float* __restrict__ beta,
             const float* __restrict__ Wq,
             const float* __restrict__ Wk,
             const float* __restrict__ Wv)
{
    __shared__ float red[16];
    const int c   = blockIdx.x;
    const int tid = threadIdx.x;
    const int warp = tid >> 5, lane = tid & 31;
    const float* Wr = (c < 64)  ? (Wq + (size_t)c * EMB)
                    : (c < 128) ? (Wk + (size_t)(c - 64) * EMB)
                                : (Wv + (size_t)(c - 128) * EMB);
    float s_w = 0.f, s_b = 0.f;
    {
        const int i4 = tid;
        float4 w = *(const float4*)(Wr + i4 * 4);
        float4 g = *(const float4*)(gamma + i4 * 4);
        float4 b = *(const float4*)(beta  + i4 * 4);
        float4 o;
        o.x = tf32r(w.x * g.x); o.y = tf32r(w.y * g.y);
        o.z = tf32r(w.z * g.z); o.w = tf32r(w.w * g.w);
        *(float4*)(g_w + (size_t)c * EMB + i4 * 4) = o;
        s_w += o.x + o.y + o.z + o.w;
        s_b += w.x*b.x + w.y*b.y + w.z*b.z + w.w*b.w;
    }
    #pragma unroll
    for (int off = 16; off; off >>= 1) {
        s_w += __shfl_xor_sync(0xffffffffu, s_w, off);
        s_b += __shfl_xor_sync(0xffffffffu, s_b, off);
    }
    if (lane == 0) { red[warp] = s_w; red[warp + 8] = s_b; }
    __syncthreads();
    if (tid == 0) {
        float aw = 0.f, ab = 0.f;
        #pragma unroll
        for (int i = 0; i < 8; i++) { aw += red[i]; ab += red[i + 8]; }
        g_wsum[c] = aw; g_wbeta[c] = ab;
    }
}

// ================= Kernel 1: QKV GEMM + in-block LN stats =================
// Block: M=64 x N=96 (2 N-halves), K chunks of 64, double-buffered cp.async.
// LN stats accumulated from the staged A tiles (no separate pass over x).
#define K1_KC 64
#define ASTR 68
#define BSTR 68
#define K1_SMEM ((2*64*ASTR + 2*96*BSTR + 128) * sizeof(float))

__global__ void __launch_bounds__(256, 2)
qkv_gemm_kernel(const float* __restrict__ x)
{
    extern __shared__ float sm1[];
    float* A_s  = sm1;                           // [2][64][68]  raw x
    float* B_s  = sm1 + 2 * 64 * ASTR;           // [2][96][68]  tf32 W'
    float* mu_s = B_s + 2 * 96 * BSTR;           // [64]
    float* rs_s = mu_s + 64;                     // [64]

    const int tid  = threadIdx.x;
    const int warp = tid >> 5;
    const int lane = tid & 31;
    const int rowBase = (blockIdx.x >> 1) * 64;
    const int nbase   = (blockIdx.x & 1) * 96;

    const uint32_t a_u = smem_u32(A_s);
    const uint32_t b_u = smem_u32(B_s);

    const int wm  = warp >> 1;   // 0..3
    const int wn  = warp & 1;    // 0..1
    const int grp = lane >> 2;
    const int tig = lane & 3;

    // stats accumulation mapping: thread -> (row, 16-wide segment)
    const int srow = tid >> 2;
    const int sseg = tid & 3;
    float psum = 0.f, psq = 0.f;

    // stage chunk 0
    {
        #pragma unroll
        for (int i = 0; i < 4; i++) {
            const int idx = tid + 256 * i;
            const int row = idx >> 4, c4 = idx & 15;
            CP_ASYNC16(a_u + (row * ASTR + c4 * 4) * 4,
                       x + (size_t)(rowBase + row) * EMB + c4 * 4);
        }
        #pragma unroll
        for (int i = 0; i < 6; i++) {
            const int idx = tid + 256 * i;
            const int c = idx >> 4, c4 = idx & 15;
            CP_ASYNC16(b_u + (c * BSTR + c4 * 4) * 4,
                       g_w + (size_t)(nbase + c) * EMB + c4 * 4);
        }
        CP_COMMIT();
    }

    float acc[6][4];
    #pragma unroll
    for (int i = 0; i < 6; i++)
        #pragma unroll
        for (int j = 0; j < 4; j++) acc[i][j] = 0.f;

    for (int ch = 0; ch < EMB / K1_KC; ch++) {
        const int buf = ch & 1;

        if (ch + 1 < EMB / K1_KC) {
            const int nb = (ch + 1) & 1;
            const int k0 = (ch + 1) * K1_KC;
            #pragma unroll
            for (int i = 0; i < 4; i++) {
                const int idx = tid + 256 * i;
                const int row = idx >> 4, c4 = idx & 15;
                CP_ASYNC16(a_u + (nb * 64 * ASTR + row * ASTR + c4 * 4) * 4,
                           x + (size_t)(rowBase + row) * EMB + k0 + c4 * 4);
            }
            #pragma unroll
            for (int i = 0; i < 6; i++) {
                const int idx = tid + 256 * i;
                const int c = idx >> 4, c4 = idx & 15;
                CP_ASYNC16(b_u + (nb * 96 * BSTR + c * BSTR + c4 * 4) * 4,
                           g_w + (size_t)(nbase + c) * EMB + k0 + c4 * 4);
            }
            CP_COMMIT();
            CP_WAIT(1);
        } else {
            CP_WAIT(0);
        }
        __syncthreads();

        const float* Ab = A_s + buf * 64 * ASTR;
        const float* Bb = B_s + buf * 96 * BSTR;

        // LN stats from the staged A tile
        {
            const float* Ar = Ab + srow * ASTR + sseg * 16;
            #pragma unroll
            for (int u = 0; u < 4; u++) {
                const float4 v = *(const float4*)(Ar + 4 * u);
                psum += v.x + v.y + v.z + v.w;
                psq  += v.x*v.x + v.y*v.y + v.z*v.z + v.w*v.w;
            }
        }

        #pragma unroll
        for (int k8 = 0; k8 < 8; k8++) {
            const int kk = k8 * 8;
            uint32_t a[4];
            const int rr = wm * 16 + grp;
            a[0] = f2tf32(Ab[rr * ASTR + kk + tig]);
            a[1] = f2tf32(Ab[(rr + 8) * ASTR + kk + tig]);
            a[2] = f2tf32(Ab[rr * ASTR + kk + tig + 4]);
            a[3] = f2tf32(Ab[(rr + 8) * ASTR + kk + tig + 4]);
            #pragma unroll
            for (int tn = 0; tn < 6; tn++) {
                const int bc = wn * 48 + tn * 8 + grp;
                const uint32_t b0 = __float_as_uint(Bb[bc * BSTR + kk + tig]);
                const uint32_t b1 = __float_as_uint(Bb[bc * BSTR + kk + tig + 4]);
                mma_tf32(acc[tn], a, b0, b1);
            }
        }
        __syncthreads();
    }

    // finalize LN stats: combine 4 segments within each quad
    psum += __shfl_xor_sync(0xffffffffu, psum, 1);
    psum += __shfl_xor_sync(0xffffffffu, psum, 2);
    psq  += __shfl_xor_sync(0xffffffffu, psq,  1);
    psq  += __shfl_xor_sync(0xffffffffu, psq,  2);
    if (sseg == 0) {
        const float inv = 1.0f / (float)EMB;
        const float mu = psum * inv;
        const float var = psq * inv - mu * mu;
        mu_s[srow] = mu;
        rs_s[srow] = rsqrtf(var + 1e-5f);
    }
    __syncthreads();

    // epilogue: out = rs*(acc - mu*wsum) + wbeta, tf32-round, scatter
    {
        const int rl = wm * 16 + grp;
        const int r0 = rowBase + rl;
        const float mu0 = mu_s[rl],     rs0 = rs_s[rl];
        const float mu1 = mu_s[rl + 8], rs1 = rs_s[rl + 8];
        #pragma unroll
        for (int tn = 0; tn < 6; tn++) {
            const int c = nbase + wn * 48 + tn * 8 + tig * 2;
            const float ws0 = g_wsum[c],   wb0 = g_wbeta[c];
            const float ws1 = g_wsum[c+1], wb1 = g_wbeta[c+1];
            float* dst = (c < 64)  ? (g_q + (size_t)r0 * HEAD + c)
                       : (c < 128) ? (g_k + (size_t)r0 * HEAD + (c - 64))
                                   : (g_v + (size_t)r0 * HEAD + (c - 128));
            *(float2*)dst = make_float2(
                tf32r(rs0 * (acc[tn][0] - mu0 * ws0) + wb0),
                tf32r(rs0 * (acc[tn][1] - mu0 * ws1) + wb1));
            *(float2*)(dst + 8 * HEAD) = make_float2(
                tf32r(rs1 * (acc[tn][2] - mu1 * ws0) + wb0),
                tf32r(rs1 * (acc[tn][3] - mu1 * ws1) + wb1));
        }
    }
}

// ================= Kernel 2: causal flash attention (tf32 mma, split-KV x4) ===
// Quarter h processes KV tiles {h, h+4, ...} <= qt. Q via LDG (no smem).
// Diagonal tile: warp w only needs key-chunks nt < 2w+2 (rest fully masked).
#define KSTR 68
#define VSTR 72
#define K2_SMEM ((2*64*KSTR + 2*64*VSTR) * sizeof(float))

__global__ void __launch_bounds__(128, 3)
attn_mma_kernel()
{
    extern __shared__ float sm2[];
    float* k_s = sm2;                   // [2][64][68]
    float* v_s = k_s + 2 * 64 * KSTR;   // [2][64][72]

    const int tid  = threadIdx.x;
    const int warp = tid >> 5;
    const int lane = tid & 31;
    const int grp  = lane >> 2;
    const int tig  = lane & 3;

    const int b  = blockIdx.x >> 7;
    const int qt = 31 - ((blockIdx.x >> 2) & 31);   // heavy tiles launch first
    const int h  = blockIdx.x & 3;
    const int qbase = qt * 64;
    const int nkv = (qt >= h) ? (((qt - h) >> 2) + 1) : 0;

    float* OM = g_om + ((size_t)h * NROWS + (size_t)b * SEQ + qbase) * HEAD;
    float* M_ = g_m + (size_t)h * NROWS + (size_t)b * SEQ + qbase;
    float* L_ = g_l + (size_t)h * NROWS + (size_t)b * SEQ + qbase;

    const int rl0 = warp * 16 + grp;
    const int rl1 = rl0 + 8;

    if (nkv == 0) {
        float4* om4 = (float4*)OM;
        for (int i = tid; i < 64 * 16; i += 128)
            om4[i] = make_float4(0.f, 0.f, 0.f, 0.f);
        if (tid < 64) { M_[tid] = -1e30f; L_[tid] = 0.f; }
        return;
    }

    const float* K = g_k + (size_t)b * SEQ * HEAD;
    const float* V = g_v + (size_t)b * SEQ * HEAD;

    const uint32_t k_u = smem_u32(k_s);
    const uint32_t v_u = smem_u32(v_s);

    {
        const float* Kg = K + (size_t)h * 64 * HEAD;
        const float* Vg = V + (size_t)h * 64 * HEAD;
        #pragma unroll
        for (int i = 0; i < 8; i++) {
            const int idx = tid + 128 * i;
            const int row = idx >> 4, c4 = idx & 15;
            CP_ASYNC16(k_u + (row * KSTR + c4 * 4) * 4, Kg + row * HEAD + c4 * 4);
            CP_ASYNC16(v_u + (row * VSTR + c4 * 4) * 4, Vg + row * HEAD + c4 * 4);
        }
        CP_COMMIT();
    }

    // Q fragments straight from gmem (already tf32; *0.125f exact)
    uint32_t qa[8][4];
    {
        const float* Qr0 = g_q + ((size_t)b * SEQ + qbase + rl0) * HEAD;
        const float* Qr1 = g_q + ((size_t)b * SEQ + qbase + rl1) * HEAD;
        #pragma unroll
        for (int kc = 0; kc < 8; kc++) {
            const int kk = kc * 8;
            qa[kc][0] = __float_as_uint(0.125f * __ldg(Qr0 + kk + tig));
            qa[kc][1] = __float_as_uint(0.125f * __ldg(Qr1 + kk + tig));
            qa[kc][2] = __float_as_uint(0.125f * __ldg(Qr0 + kk + tig + 4));
            qa[kc][3] = __float_as_uint(0.125f * __ldg(Qr1 + kk + tig + 4));
        }
    }

    float o[8][4];
    #pragma unroll
    for (int nt = 0; nt < 8; nt++)
        #pragma unroll
        for (int j = 0; j < 4; j++) o[nt][j] = 0.f;
    float m0 = -1e30f, m1 = -1e30f, l0 = 0.f, l1 = 0.f;

    const int src_lo = (grp << 2) + (tig >> 1);
    const int src_hi = src_lo + 2;

    for (int i = 0; i < nkv; i++) {
        const int kt  = h + 4 * i;
        const int buf = i & 1;
        const bool diag = (kt == qt);
        const int ntmax = diag ? (2 * warp + 2) : 8;  // key-chunks this warp needs

        if (i + 1 < nkv) {
            const int nb = (i + 1) & 1;
            const float* Kg = K + (size_t)(kt + 4) * 64 * HEAD;
            const float* Vg = V + (size_t)(kt + 4) * 64 * HEAD;
            #pragma unroll
            for (int u = 0; u < 8; u++) {
                const int idx = tid + 128 * u;
                const int row = idx >> 4, c4 = idx & 15;
                CP_ASYNC16(k_u + (nb * 64 * KSTR + row * KSTR + c4 * 4) * 4,
                           Kg + row * HEAD + c4 * 4);
                CP_ASYNC16(v_u + (nb * 64 * VSTR + row * VSTR + c4 * 4) * 4,
                           Vg + row * HEAD + c4 * 4);
            }
            CP_COMMIT();
            CP_WAIT(1);
        } else {
            CP_WAIT(0);
        }
        __syncthreads();

        const float* kb_s = k_s + buf * 64 * KSTR;
        const float* vb_s = v_s + buf * 64 * VSTR;

        // S = Q K^T (skip fully-masked key chunks on the diagonal tile)
        float s[8][4];
        #pragma unroll
        for (int nt = 0; nt < 8; nt++)
            #pragma unroll
            for (int j = 0; j < 4; j++) s[nt][j] = -1e30f;

        #pragma unroll
        for (int nt = 0; nt < 8; nt++) {
            if (nt < ntmax) {
                s[nt][0] = 0.f; s[nt][1] = 0.f; s[nt][2] = 0.f; s[nt][3] = 0.f;
                const int n = nt * 8 + grp;
                #pragma unroll
                for (int kc = 0; kc < 8; kc++) {
                    const int kk = kc * 8;
                    const uint32_t b0 = __float_as_uint(kb_s[n * KSTR + kk + tig]);
                    const uint32_t b1 = __float_as_uint(kb_s[n * KSTR + kk + tig + 4]);
                    mma_tf32(s[nt], qa[kc], b0, b1);
                }
            }
        }

        if (diag) {
            #pragma unroll
            for (int nt = 0; nt < 8; nt++) {
                if (nt < ntmax) {
                    const int c0 = nt * 8 + 2 * tig;
                    if (c0     > rl0) s[nt][0] = -1e30f;
                    if (c0 + 1 > rl0) s[nt][1] = -1e30f;
                    if (c0     > rl1) s[nt][2] = -1e30f;
                    if (c0 + 1 > rl1) s[nt][3] = -1e30f;
                }
            }
        }

        // online softmax (register/quad only)
        float mx0 = -1e30f, mx1 = -1e30f;
        #pragma unroll
        for (int nt = 0; nt < 8; nt++) {
            if (nt < ntmax) {
                mx0 = fmaxf(mx0, fmaxf(s[nt][0], s[nt][1]));
                mx1 = fmaxf(mx1, fmaxf(s[nt][2], s[nt][3]));
            }
        }
        mx0 = fmaxf(mx0, __shfl_xor_sync(0xffffffffu, mx0, 1));
        mx0 = fmaxf(mx0, __shfl_xor_sync(0xffffffffu, mx0, 2));
        mx1 = fmaxf(mx1, __shfl_xor_sync(0xffffffffu, mx1, 1));
        mx1 = fmaxf(mx1, __shfl_xor_sync(0xffffffffu, mx1, 2));

        const float mn0 = fmaxf(m0, mx0);
        const float mn1 = fmaxf(m1, mx1);
        const float cor0 = __expf(m0 - mn0);
        const float cor1 = __expf(m1 - mn1);
        m0 = mn0; m1 = mn1;

        float sum0 = 0.f, sum1 = 0.f;
        #pragma unroll
        for (int nt = 0; nt < 8; nt++) {
            if (nt < ntmax) {
                s[nt][0] = __expf(s[nt][0] - mn0);
                s[nt][1] = __expf(s[nt][1] - mn0);
                s[nt][2] = __expf(s[nt][2] - mn1);
                s[nt][3] = __expf(s[nt][3] - mn1);
                sum0 += s[nt][0] + s[nt][1];
                sum1 += s[nt][2] + s[nt][3];
            }
        }
        sum0 += __shfl_xor_sync(0xffffffffu, sum0, 1);
        sum0 += __shfl_xor_sync(0xffffffffu, sum0, 2);
        sum1 += __shfl_xor_sync(0xffffffffu, sum1, 1);
        sum1 += __shfl_xor_sync(0xffffffffu, sum1, 2);
        l0 = l0 * cor0 + sum0;
        l1 = l1 * cor1 + sum1;

        #pragma unroll
        for (int nt = 0; nt < 8; nt++) {
            o[nt][0] *= cor0; o[nt][1] *= cor0;
            o[nt][2] *= cor1; o[nt][3] *= cor1;
        }

        // P -> A-frag (skip masked key chunks) then O += P V
        #pragma unroll
        for (int kc = 0; kc < 8; kc++) {
            if (kc < ntmax) {
                uint32_t pa[4];
                const float v0 = __shfl_sync(0xffffffffu, s[kc][0], src_lo);
                const float v1 = __shfl_sync(0xffffffffu, s[kc][1], src_lo);
                const float v2 = __shfl_sync(0xffffffffu, s[kc][2], src_lo);
                const float v3 = __shfl_sync(0xffffffffu, s[kc][3], src_lo);
                const float w0 = __shfl_sync(0xffffffffu, s[kc][0], src_hi);
                const float w1 = __shfl_sync(0xffffffffu, s[kc][1], src_hi);
                const float w2 = __shfl_sync(0xffffffffu, s[kc][2], src_hi);
                const float w3 = __shfl_sync(0xffffffffu, s[kc][3], src_hi);
                pa[0] = f2tf32((tig & 1) ? v1 : v0);
                pa[1] = f2tf32((tig & 1) ? v3 : v2);
                pa[2] = f2tf32((tig & 1) ? w1 : w0);
                pa[3] = f2tf32((tig & 1) ? w3 : w2);

                const int k0 = kc * 8;
                #pragma unroll
                for (int nt = 0; nt < 8; nt++) {
                    const int n = nt * 8 + grp;
                    const uint32_t b0 = __float_as_uint(vb_s[(k0 + tig) * VSTR + n]);
                    const uint32_t b1 = __float_as_uint(vb_s[(k0 + tig + 4) * VSTR + n]);
                    mma_tf32(o[nt], pa, b0, b1);
                }
            }
        }

        __syncthreads();
    }

    // epilogue: unnormalized partials + stats
    #pragma unroll
    for (int nt = 0; nt < 8; nt++) {
        const int c = nt * 8 + 2 * tig;
        *(float2*)(OM + (size_t)rl0 * HEAD + c) = make_float2(o[nt][0], o[nt][1]);
        *(float2*)(OM + (size_t)rl1 * HEAD + c) = make_float2(o[nt][2], o[nt][3]);
    }
    if (tig == 0) {
        M_[rl0] = m0; L_[rl0] = l0;
        M_[rl1] = m1; L_[rl1] = l1;
    }
}

// ================= Kernel 3: split-KV combine (4 partials) =================
__global__ void __launch_bounds__(256)
combine_kernel(float* __restrict__ out)
{
    const int idx = blockIdx.x * 256 + threadIdx.x;
    const int row = idx >> 4;
    const int c4  = idx & 15;

    float m[SPLITK], l[SPLITK];
    float M = -1e30f;
    #pragma unroll
    for (int h = 0; h < SPLITK; h++) {
        m[h] = g_m[h * NROWS + row];
        l[h] = g_l[h * NROWS + row];
        M = fmaxf(M, m[h]);
    }
    float denom = 0.f, a[SPLITK];
    #pragma unroll
    for (int h = 0; h < SPLITK; h++) {
        a[h] = __expf(m[h] - M);
        denom += l[h] * a[h];
    }
    const float inv = 1.0f / denom;

    float4 r = make_float4(0.f, 0.f, 0.f, 0.f);
    #pragma unroll
    for (int h = 0; h < SPLITK; h++) {
        const float w = a[h] * inv;
        const float4 oh = *(const float4*)(g_om + ((size_t)h * NROWS + row) * HEAD + c4 * 4);
        r.x += oh.x * w; r.y += oh.y * w;
        r.z += oh.z * w; r.w += oh.w * w;
    }
    *(float4*)(out + (size_t)row * HEAD + c4 * 4) = r;
}

// ================= launch =================
extern "C" void kernel_launch(void* const* d_in, const int* in_sizes, int n_in,
                              void* d_out, int out_size)
{
    const float* x     = (const float*)d_in[0];
    const float* gamma = (const float*)d_in[1];
    const float* beta  = (const float*)d_in[2];
    const float* Wq    = (const float*)d_in[3];
    const float* Wk    = (const float*)d_in[4];
    const float* Wv    = (const float*)d_in[5];
    float* out = (float*)d_out;

    cudaFuncSetAttribute(qkv_gemm_kernel, cudaFuncAttributeMaxDynamicSharedMemorySize, (int)K1_SMEM);
    cudaFuncSetAttribute(attn_mma_kernel, cudaFuncAttributeMaxDynamicSharedMemorySize, (int)K2_SMEM);

    wprep_kernel<<<192, 256>>>(gamma, beta, Wq, Wk, Wv);
    qkv_gemm_kernel<<<(NROWS / 64) * 2, 256, K1_SMEM>>>(x);
    attn_mma_kernel<<<BATCH * 32 * SPLITK, 128, K2_SMEM>>>();
    combine_kernel<<<NROWS * 16 / 256, 256>>>(out);
}

// round 9
// speedup vs baseline: 1.4085x; 1.4085x over previous
#include <cuda_runtime.h>
#include <cuda_fp16.h>
#include <stdint.h>
#include <math.h>

// Problem constants
#define BATCH 4
#define SEQ   2048
#define EMB   1024
#define HEAD  64
#define NROWS (BATCH * SEQ)   // 8192
#define SPLITK 4

// ---------------- scratch ----------------
__device__ __half g_qh[NROWS * HEAD];          // fp16, pre-scaled by 1/8
__device__ __half g_kh[NROWS * HEAD];          // fp16
__device__ __half g_vth[NROWS * HEAD];         // fp16, per-64-tile transposed [tile][head][key]
__device__ float  g_om[SPLITK * NROWS * HEAD];
__device__ float  g_m [SPLITK * NROWS];
__device__ float  g_l [SPLITK * NROWS];
__device__ float  g_mu[NROWS];
__device__ float  g_rs[NROWS];
__device__ __half g_wh[192 * EMB];             // gamma-folded fp16 weights (q|k|v)
__device__ float  g_wsum [192];                // sum of fp16 W' values
__device__ float  g_wbeta[192];                // sum W*beta

__device__ __forceinline__ uint32_t pack_h2(float lo, float hi) {
    __half2 h = __floats2half2_rn(lo, hi);
    return *reinterpret_cast<uint32_t*>(&h);
}

__device__ __forceinline__ void mma_f16(float* d, const uint32_t* a,
                                        uint32_t b0, uint32_t b1) {
    asm volatile(
        "mma.sync.aligned.m16n8k16.row.col.f32.f16.f16.f32 "
        "{%0,%1,%2,%3}, {%4,%5,%6,%7}, {%8,%9}, {%0,%1,%2,%3};"
        : "+f"(d[0]), "+f"(d[1]), "+f"(d[2]), "+f"(d[3])
        : "r"(a[0]), "r"(a[1]), "r"(a[2]), "r"(a[3]), "r"(b0), "r"(b1));
}

__device__ __forceinline__ uint32_t smem_u32(const void* p) {
    return (uint32_t)__cvta_generic_to_shared(p);
}

#define CP_ASYNC16(dst_u32, src_ptr) \
    asm volatile("cp.async.cg.shared.global [%0], [%1], 16;" \
                 :: "r"(dst_u32), "l"(src_ptr))
#define CP_COMMIT() asm volatile("cp.async.commit_group;")
#define CP_WAIT(N)  asm volatile("cp.async.wait_group %0;" :: "n"(N))

// ================= Kernel 0a: LayerNorm stats =================
__global__ void __launch_bounds__(256)
ln_stats_kernel(const float* __restrict__ x)
{
    const int warp = threadIdx.x >> 5;
    const int lane = threadIdx.x & 31;
    const int r = blockIdx.x * 8 + warp;
    const float4* xr = (const float4*)(x + (size_t)r * EMB);
    float sum = 0.f, sq = 0.f;
    #pragma unroll
    for (int t = 0; t < 8; t++) {
        float4 v = xr[lane + 32 * t];
        sum += v.x + v.y + v.z + v.w;
        sq  += v.x*v.x + v.y*v.y + v.z*v.z + v.w*v.w;
    }
    #pragma unroll
    for (int off = 16; off; off >>= 1) {
        sum += __shfl_xor_sync(0xffffffffu, sum, off);
        sq  += __shfl_xor_sync(0xffffffffu, sq,  off);
    }
    if (lane == 0) {
        const float inv = 1.0f / (float)EMB;
        const float mu = sum * inv;
        const float var = sq * inv - mu * mu;
        g_mu[r] = mu;
        g_rs[r] = rsqrtf(var + 1e-5f);
    }
}

// ================= Kernel 0b: weight prep (fold gamma, fp16) =================
__global__ void __launch_bounds__(256)
wprep_kernel(const float* __restrict__ gamma,
             const float* __restrict__ beta,
             const float* __restrict__ Wq,
             const float* __restrict__ Wk,
             const float* __restrict__ Wv)
{
    __shared__ float red[16];
    const int c   = blockIdx.x;
    const int tid = threadIdx.x;
    const int warp = tid >> 5, lane = tid & 31;
    const float* Wr = (c < 64)  ? (Wq + (size_t)c * EMB)
                    : (c < 128) ? (Wk + (size_t)(c - 64) * EMB)
                                : (Wv + (size_t)(c - 128) * EMB);
    float s_w = 0.f, s_b = 0.f;
    {
        float4 w = *(const float4*)(Wr + tid * 4);
        float4 g = *(const float4*)(gamma + tid * 4);
        float4 b = *(const float4*)(beta  + tid * 4);
        __half h0 = __float2half_rn(w.x * g.x);
        __half h1 = __float2half_rn(w.y * g.y);
        __half h2 = __float2half_rn(w.z * g.z);
        __half h3 = __float2half_rn(w.w * g.w);
        __half2 p0 = __halves2half2(h0, h1);
        __half2 p1 = __halves2half2(h2, h3);
        uint2 st;
        st.x = *reinterpret_cast<uint32_t*>(&p0);
        st.y = *reinterpret_cast<uint32_t*>(&p1);
        *reinterpret_cast<uint2*>(g_wh + (size_t)c * EMB + tid * 4) = st;
        s_w += __half2float(h0) + __half2float(h1) + __half2float(h2) + __half2float(h3);
        s_b += w.x*b.x + w.y*b.y + w.z*b.z + w.w*b.w;
    }
    #pragma unroll
    for (int off = 16; off; off >>= 1) {
        s_w += __shfl_xor_sync(0xffffffffu, s_w, off);
        s_b += __shfl_xor_sync(0xffffffffu, s_b, off);
    }
    if (lane == 0) { red[warp] = s_w; red[warp + 8] = s_b; }
    __syncthreads();
    if (tid == 0) {
        float aw = 0.f, ab = 0.f;
        #pragma unroll
        for (int i = 0; i < 8; i++) { aw += red[i]; ab += red[i + 8]; }
        g_wsum[c] = aw; g_wbeta[c] = ab;
    }
}

// ================= Kernel 1: QKV GEMM (fp16 mma, LN in epilogue) =============
// Block: M=64 x N=96 (2 N-halves), K chunks of 64, double-buffered cp.async.
#define K1_KC 64
#define ASTR 68      // fp32 x tile stride
#define BSTR2 72     // fp16 weight tile stride (halves); word bank = 4*grp+tig
#define K1_SMEM (2*64*ASTR*4 + 2*96*BSTR2*2)

__global__ void __launch_bounds__(256, 2)
qkv_gemm_kernel(const float* __restrict__ x)
{
    extern __shared__ char sm1[];
    float*  A_s = (float*)sm1;                        // [2][64][68] fp32 raw x
    __half* B_s = (__half*)(sm1 + 2*64*ASTR*4);       // [2][96][72] fp16 W'

    const int tid  = threadIdx.x;
    const int warp = tid >> 5;
    const int lane = tid & 31;
    const int rowBase = (blockIdx.x >> 1) * 64;
    const int nbase   = (blockIdx.x & 1) * 96;

    const uint32_t a_u = smem_u32(A_s);
    const uint32_t b_u = smem_u32(B_s);

    const int wm  = warp >> 1;   // 0..3
    const int wn  = warp & 1;    // 0..1
    const int grp = lane >> 2;
    const int tig = lane & 3;

    // stage chunk 0
    {
        #pragma unroll
        for (int i = 0; i < 4; i++) {
            const int idx = tid + 256 * i;
            const int row = idx >> 4, c4 = idx & 15;
            CP_ASYNC16(a_u + (row * ASTR + c4 * 4) * 4,
                       x + (size_t)(rowBase + row) * EMB + c4 * 4);
        }
        #pragma unroll
        for (int i = 0; i < 3; i++) {
            const int idx = tid + 256 * i;           // 0..767
            const int c = idx >> 3, c8 = idx & 7;
            CP_ASYNC16(b_u + (c * BSTR2 + c8 * 8) * 2,
                       g_wh + (size_t)(nbase + c) * EMB + c8 * 8);
        }
        CP_COMMIT();
    }

    float acc[6][4];
    #pragma unroll
    for (int i = 0; i < 6; i++)
        #pragma unroll
        for (int j = 0; j < 4; j++) acc[i][j] = 0.f;

    for (int ch = 0; ch < EMB / K1_KC; ch++) {
        const int buf = ch & 1;

        if (ch + 1 < EMB / K1_KC) {
            const int nb = (ch + 1) & 1;
            const int k0 = (ch + 1) * K1_KC;
            #pragma unroll
            for (int i = 0; i < 4; i++) {
                const int idx = tid + 256 * i;
                const int row = idx >> 4, c4 = idx & 15;
                CP_ASYNC16(a_u + (nb * 64 * ASTR + row * ASTR + c4 * 4) * 4,
                           x + (size_t)(rowBase + row) * EMB + k0 + c4 * 4);
            }
            #pragma unroll
            for (int i = 0; i < 3; i++) {
                const int idx = tid + 256 * i;
                const int c = idx >> 3, c8 = idx & 7;
                CP_ASYNC16(b_u + (nb * 96 * BSTR2 + c * BSTR2 + c8 * 8) * 2,
                           g_wh + (size_t)(nbase + c) * EMB + k0 + c8 * 8);
            }
            CP_COMMIT();
            CP_WAIT(1);
        } else {
            CP_WAIT(0);
        }
        __syncthreads();

        const float*  Ab = A_s + buf * 64 * ASTR;
        const __half* Bb = B_s + buf * 96 * BSTR2;

        #pragma unroll
        for (int k16 = 0; k16 < 4; k16++) {
            const int kk = k16 * 16;
            const int rr = wm * 16 + grp;
            // A-frag: fp32 pairs -> fp16x2 packs
            const float2 f0 = *(const float2*)(Ab + rr * ASTR + kk + 2 * tig);
            const float2 f1 = *(const float2*)(Ab + (rr + 8) * ASTR + kk + 2 * tig);
            const float2 f2 = *(const float2*)(Ab + rr * ASTR + kk + 8 + 2 * tig);
            const float2 f3 = *(const float2*)(Ab + (rr + 8) * ASTR + kk + 8 + 2 * tig);
            uint32_t a[4];
            a[0] = pack_h2(f0.x, f0.y);
            a[1] = pack_h2(f1.x, f1.y);
            a[2] = pack_h2(f2.x, f2.y);
            a[3] = pack_h2(f3.x, f3.y);
            #pragma unroll
            for (int tn = 0; tn < 6; tn++) {
                const int bc = wn * 48 + tn * 8 + grp;
                const uint32_t b0 = *(const uint32_t*)(Bb + bc * BSTR2 + kk + 2 * tig);
                const uint32_t b1 = *(const uint32_t*)(Bb + bc * BSTR2 + kk + 8 + 2 * tig);
                mma_f16(acc[tn], a, b0, b1);
            }
        }
        __syncthreads();
    }

    // epilogue: out = rs*(acc - mu*wsum) + wbeta; q scaled 1/8; v transposed
    {
        const int rl = wm * 16 + grp;
        const int r0 = rowBase + rl;
        const int tile = blockIdx.x >> 1;
        const float mu0 = g_mu[r0],     rs0 = g_rs[r0];
        const float mu1 = g_mu[r0 + 8], rs1 = g_rs[r0 + 8];
        #pragma unroll
        for (int tn = 0; tn < 6; tn++) {
            const int c = nbase + wn * 48 + tn * 8 + tig * 2;
            const float ws0 = g_wsum[c],   wb0 = g_wbeta[c];
            const float ws1 = g_wsum[c+1], wb1 = g_wbeta[c+1];
            const float v00 = rs0 * (acc[tn][0] - mu0 * ws0) + wb0;
            const float v01 = rs0 * (acc[tn][1] - mu0 * ws1) + wb1;
            const float v10 = rs1 * (acc[tn][2] - mu1 * ws0) + wb0;
            const float v11 = rs1 * (acc[tn][3] - mu1 * ws1) + wb1;
            if (c < 64) {          // Q, pre-scaled by 1/8
                __half* dst = g_qh + (size_t)r0 * HEAD + c;
                *(uint32_t*)dst            = pack_h2(v00 * 0.125f, v01 * 0.125f);
                *(uint32_t*)(dst + 8*HEAD) = pack_h2(v10 * 0.125f, v11 * 0.125f);
            } else if (c < 128) {  // K
                __half* dst = g_kh + (size_t)r0 * HEAD + (c - 64);
                *(uint32_t*)dst            = pack_h2(v00, v01);
                *(uint32_t*)(dst + 8*HEAD) = pack_h2(v10, v11);
            } else {               // V transposed: [tile][head][key]
                const int h = c - 128;
                __half* vt = g_vth + (size_t)tile * 4096;
                vt[(h    ) * 64 + rl    ] = __float2half_rn(v00);
                vt[(h + 1) * 64 + rl    ] = __float2half_rn(v01);
                vt[(h    ) * 64 + rl + 8] = __float2half_rn(v10);
                vt[(h + 1) * 64 + rl + 8] = __float2half_rn(v11);
            }
        }
    }
}

// ================= Kernel 2: causal flash attention (fp16 mma, split-KV x4) ===
// Quarter h: KV tiles {h, h+4, ...} <= qt. Q via LDG. K/V fp16 in smem.
#define KSTR2 72   // halves; word bank = 4*grp + tig : conflict-free
#define VSTR2 72
#define K2_SMEM ((2*64*KSTR2 + 2*64*VSTR2) * 2)

__global__ void __launch_bounds__(128, 4)
attn_mma_kernel()
{
    extern __shared__ char sm2[];
    __half* k_s = (__half*)sm2;                       // [2][64][72]
    __half* v_s = (__half*)(sm2 + 2*64*KSTR2*2);      // [2][64][72] transposed tiles

    const int tid  = threadIdx.x;
    const int warp = tid >> 5;
    const int lane = tid & 31;
    const int grp  = lane >> 2;
    const int tig  = lane & 3;

    const int b  = blockIdx.x >> 7;
    const int qt = 31 - ((blockIdx.x >> 2) & 31);   // heavy tiles launch first
    const int h  = blockIdx.x & 3;
    const int qbase = qt * 64;
    const int nkv = (qt >= h) ? (((qt - h) >> 2) + 1) : 0;

    float* OM = g_om + ((size_t)h * NROWS + (size_t)b * SEQ + qbase) * HEAD;
    float* M_ = g_m + (size_t)h * NROWS + (size_t)b * SEQ + qbase;
    float* L_ = g_l + (size_t)h * NROWS + (size_t)b * SEQ + qbase;

    const int rl0 = warp * 16 + grp;
    const int rl1 = rl0 + 8;

    if (nkv == 0) {
        float4* om4 = (float4*)OM;
        for (int i = tid; i < 64 * 16; i += 128)
            om4[i] = make_float4(0.f, 0.f, 0.f, 0.f);
        if (tid < 64) { M_[tid] = -1e30f; L_[tid] = 0.f; }
        return;
    }

    const __half* K  = g_kh  + (size_t)b * SEQ * HEAD;
    const __half* VT = g_vth + (size_t)(b * 32) * 4096;

    const uint32_t k_u = smem_u32(k_s);
    const uint32_t v_u = smem_u32(v_s);

    // prefetch first KV tile (index h): 64 rows x 128B each
    {
        const __half* Kg = K  + (size_t)h * 64 * HEAD;
        const __half* Vg = VT + (size_t)h * 4096;
        #pragma unroll
        for (int i = 0; i < 4; i++) {
            const int idx = tid + 128 * i;
            const int row = idx >> 3, c8 = idx & 7;
            CP_ASYNC16(k_u + (row * KSTR2 + c8 * 8) * 2, Kg + row * HEAD + c8 * 8);
            CP_ASYNC16(v_u + (row * VSTR2 + c8 * 8) * 2, Vg + row * 64 + c8 * 8);
        }
        CP_COMMIT();
    }

    // Q fragments straight from gmem (fp16, pre-scaled by 1/8)
    uint32_t qa[4][4];
    {
        const __half* Qr0 = g_qh + ((size_t)b * SEQ + qbase + rl0) * HEAD;
        const __half* Qr1 = g_qh + ((size_t)b * SEQ + qbase + rl1) * HEAD;
        #pragma unroll
        for (int kc = 0; kc < 4; kc++) {
            const int kk = kc * 16;
            qa[kc][0] = __ldg((const uint32_t*)(Qr0 + kk + 2 * tig));
            qa[kc][1] = __ldg((const uint32_t*)(Qr1 + kk + 2 * tig));
            qa[kc][2] = __ldg((const uint32_t*)(Qr0 + kk + 8 + 2 * tig));
            qa[kc][3] = __ldg((const uint32_t*)(Qr1 + kk + 8 + 2 * tig));
        }
    }

    float o[8][4];
    #pragma unroll
    for (int nt = 0; nt < 8; nt++)
        #pragma unroll
        for (int j = 0; j < 4; j++) o[nt][j] = 0.f;
    float m0 = -1e30f, m1 = -1e30f, l0 = 0.f, l1 = 0.f;

    for (int i = 0; i < nkv; i++) {
        const int kt  = h + 4 * i;
        const int buf = i & 1;

        if (i + 1 < nkv) {
            const int nb = (i + 1) & 1;
            const __half* Kg = K  + (size_t)(kt + 4) * 64 * HEAD;
            const __half* Vg = VT + (size_t)(kt + 4) * 4096;
            #pragma unroll
            for (int u = 0; u < 4; u++) {
                const int idx = tid + 128 * u;
                const int row = idx >> 3, c8 = idx & 7;
                CP_ASYNC16(k_u + (nb * 64 * KSTR2 + row * KSTR2 + c8 * 8) * 2,
                           Kg + row * HEAD + c8 * 8);
                CP_ASYNC16(v_u + (nb * 64 * VSTR2 + row * VSTR2 + c8 * 8) * 2,
                           Vg + row * 64 + c8 * 8);
            }
            CP_COMMIT();
            CP_WAIT(1);
        } else {
            CP_WAIT(0);
        }
        __syncthreads();

        const __half* kb_s = k_s + buf * 64 * KSTR2;
        const __half* vb_s = v_s + buf * 64 * VSTR2;

        // ---- S = Q K^T (fp16 m16n8k16) ----
        float s[8][4];
        #pragma unroll
        for (int nt = 0; nt < 8; nt++)
            #pragma unroll
            for (int j = 0; j < 4; j++) s[nt][j] = 0.f;

        #pragma unroll
        for (int kc = 0; kc < 4; kc++) {
            const int kk = kc * 16;
            #pragma unroll
            for (int nt = 0; nt < 8; nt++) {
                const int n = nt * 8 + grp;
                const uint32_t b0 = *(const uint32_t*)(kb_s + n * KSTR2 + kk + 2 * tig);
                const uint32_t b1 = *(const uint32_t*)(kb_s + n * KSTR2 + kk + 8 + 2 * tig);
                mma_f16(s[nt], qa[kc], b0, b1);
            }
        }

        // ---- causal mask on the diagonal tile ----
        if (kt == qt) {
            #pragma unroll
            for (int nt = 0; nt < 8; nt++) {
                const int c0 = nt * 8 + 2 * tig;
                if (c0     > rl0) s[nt][0] = -1e30f;
                if (c0 + 1 > rl0) s[nt][1] = -1e30f;
                if (c0     > rl1) s[nt][2] = -1e30f;
                if (c0 + 1 > rl1) s[nt][3] = -1e30f;
            }
        }

        // ---- online softmax (register/quad only) ----
        float mx0 = -1e30f, mx1 = -1e30f;
        #pragma unroll
        for (int nt = 0; nt < 8; nt++) {
            mx0 = fmaxf(mx0, fmaxf(s[nt][0], s[nt][1]));
            mx1 = fmaxf(mx1, fmaxf(s[nt][2], s[nt][3]));
        }
        mx0 = fmaxf(mx0, __shfl_xor_sync(0xffffffffu, mx0, 1));
        mx0 = fmaxf(mx0, __shfl_xor_sync(0xffffffffu, mx0, 2));
        mx1 = fmaxf(mx1, __shfl_xor_sync(0xffffffffu, mx1, 1));
        mx1 = fmaxf(mx1, __shfl_xor_sync(0xffffffffu, mx1, 2));

        const float mn0 = fmaxf(m0, mx0);
        const float mn1 = fmaxf(m1, mx1);
        const float cor0 = __expf(m0 - mn0);
        const float cor1 = __expf(m1 - mn1);
        m0 = mn0; m1 = mn1;

        float sum0 = 0.f, sum1 = 0.f;
        #pragma unroll
        for (int nt = 0; nt < 8; nt++) {
            s[nt][0] = __expf(s[nt][0] - mn0);
            s[nt][1] = __expf(s[nt][1] - mn0);
            s[nt][2] = __expf(s[nt][2] - mn1);
            s[nt][3] = __expf(s[nt][3] - mn1);
            sum0 += s[nt][0] + s[nt][1];
            sum1 += s[nt][2] + s[nt][3];
        }
        sum0 += __shfl_xor_sync(0xffffffffu, sum0, 1);
        sum0 += __shfl_xor_sync(0xffffffffu, sum0, 2);
        sum1 += __shfl_xor_sync(0xffffffffu, sum1, 1);
        sum1 += __shfl_xor_sync(0xffffffffu, sum1, 2);
        l0 = l0 * cor0 + sum0;
        l1 = l1 * cor1 + sum1;

        #pragma unroll
        for (int nt = 0; nt < 8; nt++) {
            o[nt][0] *= cor0; o[nt][1] *= cor0;
            o[nt][2] *= cor1; o[nt][3] *= cor1;
        }

        // ---- O += P V : fp16 C-frag == A-frag layout, NO shuffles ----
        #pragma unroll
        for (int kc = 0; kc < 4; kc++) {
            uint32_t pa[4];
            pa[0] = pack_h2(s[2*kc][0],     s[2*kc][1]);
            pa[1] = pack_h2(s[2*kc][2],     s[2*kc][3]);
            pa[2] = pack_h2(s[2*kc + 1][0], s[2*kc + 1][1]);
            pa[3] = pack_h2(s[2*kc + 1][2], s[2*kc + 1][3]);
            const int kk = kc * 16;
            #pragma unroll
            for (int nt = 0; nt < 8; nt++) {
                const int n = nt * 8 + grp;
                const uint32_t b0 = *(const uint32_t*)(vb_s + n * VSTR2 + kk + 2 * tig);
                const uint32_t b1 = *(const uint32_t*)(vb_s + n * VSTR2 + kk + 8 + 2 * tig);
                mma_f16(o[nt], pa, b0, b1);
            }
        }

        __syncthreads();
    }

    // epilogue: unnormalized partials + stats
    #pragma unroll
    for (int nt = 0; nt < 8; nt++) {
        const int c = nt * 8 + 2 * tig;
        *(float2*)(OM + (size_t)rl0 * HEAD + c) = make_float2(o[nt][0], o[nt][1]);
        *(float2*)(OM + (size_t)rl1 * HEAD + c) = make_float2(o[nt][2], o[nt][3]);
    }
    if (tig == 0) {
        M_[rl0] = m0; L_[rl0] = l0;
        M_[rl1] = m1; L_[rl1] = l1;
    }
}

// ================= Kernel 3: split-KV combine (4 partials) =================
__global__ void __launch_bounds__(256)
combine_kernel(float* __restrict__ out)
{
    const int idx = blockIdx.x * 256 + threadIdx.x;
    const int row = idx >> 4;
    const int c4  = idx & 15;

    float m[SPLITK], l[SPLITK];
    float M = -1e30f;
    #pragma unroll
    for (int h = 0; h < SPLITK; h++) {
        m[h] = g_m[h * NROWS + row];
        l[h] = g_l[h * NROWS + row];
        M = fmaxf(M, m[h]);
    }
    float denom = 0.f, a[SPLITK];
    #pragma unroll
    for (int h = 0; h < SPLITK; h++) {
        a[h] = __expf(m[h] - M);
        denom += l[h] * a[h];
    }
    const float inv = 1.0f / denom;

    float4 r = make_float4(0.f, 0.f, 0.f, 0.f);
    #pragma unroll
    for (int h = 0; h < SPLITK; h++) {
        const float w = a[h] * inv;
        const float4 oh = *(const float4*)(g_om + ((size_t)h * NROWS + row) * HEAD + c4 * 4);
        r.x += oh.x * w; r.y += oh.y * w;
        r.z += oh.z * w; r.w += oh.w * w;
    }
    *(float4*)(out + (size_t)row * HEAD + c4 * 4) = r;
}

// ================= launch =================
extern "C" void kernel_launch(void* const* d_in, const int* in_sizes, int n_in,
                              void* d_out, int out_size)
{
    const float* x     = (const float*)d_in[0];
    const float* gamma = (const float*)d_in[1];
    const float* beta  = (const float*)d_in[2];
    const float* Wq    = (const float*)d_in[3];
    const float* Wk    = (const float*)d_in[4];
    const float* Wv    = (const float*)d_in[5];
    float* out = (float*)d_out;

    cudaFuncSetAttribute(qkv_gemm_kernel, cudaFuncAttributeMaxDynamicSharedMemorySize, (int)K1_SMEM);
    cudaFuncSetAttribute(attn_mma_kernel, cudaFuncAttributeMaxDynamicSharedMemorySize, (int)K2_SMEM);

    ln_stats_kernel<<<NROWS / 8, 256>>>(x);
    wprep_kernel<<<192, 256>>>(gamma, beta, Wq, Wk, Wv);
    qkv_gemm_kernel<<<(NROWS / 64) * 2, 256, K1_SMEM>>>(x);
    attn_mma_kernel<<<BATCH * 32 * SPLITK, 128, K2_SMEM>>>();
    combine_kernel<<<NROWS * 16 / 256, 256>>>(out);
}